// round 14
// baseline (speedup 1.0000x reference)
#include <cuda_runtime.h>
#include <math.h>
#include <stdint.h>

#define B_  32
#define S1_ 128
#define T_  50
#define E_  768
#define H_  1024
#define V_  32000

// ---------------- device scratch (no allocation allowed) ----------------
__device__ float g_xW[B_ * S1_ * H_];      // x @ W1x^T (precomputed once)
__device__ float g_inp0[B_ * 2 * E_];      // [emb_t ; context]
__device__ float g_h[3 * B_ * H_];
__device__ float g_c[3 * B_ * H_];
__device__ float g_bsum[3 * 4 * H_];       // bih + bhh per layer
__device__ float g_part[16 * B_ * 4 * H_]; // split-K partials
__device__ float g_fcpart[2 * 4 * B_ * V_];// fc partials, double-buffered sets
__device__ int           g_barCnt;         // monotonic arrival counter
__device__ volatile int  g_barRel;         // last released epoch

// ---------------- f32x2 packed helpers ----------------
__device__ __forceinline__ unsigned long long ffma2_(unsigned long long a,
                                                     unsigned long long b,
                                                     unsigned long long c) {
    unsigned long long d;
    asm("fma.rn.f32x2 %0, %1, %2, %3;" : "=l"(d) : "l"(a), "l"(b), "l"(c));
    return d;
}
__device__ __forceinline__ unsigned long long bcast2_(float x) {
    unsigned long long r;
    asm("mov.b64 %0, {%1, %1};" : "=l"(r) : "f"(x));
    return r;
}
__device__ __forceinline__ void unpack2_(unsigned long long v, float& lo, float& hi) {
    asm("mov.b64 {%0, %1}, %2;" : "=f"(lo), "=f"(hi) : "l"(v));
}
__device__ __forceinline__ float tf32r(float x) {
    unsigned u;
    asm("cvt.rna.tf32.f32 %0, %1;" : "=r"(u) : "f"(x));
    return __uint_as_float(u);
}

#define SHA_STRIDE 1152   // 32*36
#define SHW_STRIDE 2112   // 32*66

// ---------------- grid barrier: monotonic epoch (no reset race) ----------
__device__ __forceinline__ void gbar(int* sepoch)
{
    __syncthreads();
    __threadfence();                       // release prior writes
    if (threadIdx.x == 0) {
        const int e      = ++(*sepoch);
        const int target = e * (int)gridDim.x;
        const int v      = atomicAdd(&g_barCnt, 1) + 1;
        if (v == target) g_barRel = e;
        else { while (g_barRel < e) __nanosleep(64); }
    }
    __syncthreads();
    __threadfence();                       // acquire
}

// ---------------- shared GEMM core: 32 rows x 64 cols, 128 threads --------
// Ping-pong double-buffered smem, one __syncthreads per K-chunk.
__device__ __forceinline__ void gemm_core32(
    const float* __restrict__ A, int ldA,
    const float* __restrict__ W, int ldW,
    int kbase, int NC, int nbase,
    float* __restrict__ dst, int Nout,
    float* shA, float* shW)
{
    const int tid = threadIdx.x;
    const int ng  = tid & 31;
    const int mg  = tid >> 5;
    const int m0  = mg * 8;

    unsigned long long acc0[4], acc1[4];
#pragma unroll
    for (int r = 0; r < 4; r++) { acc0[r] = 0ull; acc1[r] = 0ull; }

    float4 aR[2], wR[4];
    auto loadChunk = [&](int c) {
        const int k0 = kbase + c * 32;
#pragma unroll
        for (int j = 0; j < 2; j++) {
            const int f4 = tid + j * 128;
            const int m  = f4 >> 3, kq = f4 & 7;
            aR[j] = *reinterpret_cast<const float4*>(&A[(size_t)m * ldA + k0 + kq * 4]);
        }
#pragma unroll
        for (int j = 0; j < 4; j++) {
            const int f4 = tid + j * 128;
            const int r  = f4 >> 3, kq = f4 & 7;
            wR[j] = *reinterpret_cast<const float4*>(
                &W[(size_t)(nbase + r) * ldW + k0 + kq * 4]);
        }
    };

    loadChunk(0);
    for (int c = 0; c < NC; c++) {
        float* sA = shA + (c & 1) * SHA_STRIDE;
        float* sW = shW + (c & 1) * SHW_STRIDE;
#pragma unroll
        for (int j = 0; j < 2; j++) {
            const int f4 = tid + j * 128;
            const int m  = f4 >> 3, kq = f4 & 7;
            sA[(kq * 4 + 0) * 36 + m] = tf32r(aR[j].x);
            sA[(kq * 4 + 1) * 36 + m] = tf32r(aR[j].y);
            sA[(kq * 4 + 2) * 36 + m] = tf32r(aR[j].z);
            sA[(kq * 4 + 3) * 36 + m] = tf32r(aR[j].w);
        }
#pragma unroll
        for (int j = 0; j < 4; j++) {
            const int f4 = tid + j * 128;
            const int r  = f4 >> 3, kq = f4 & 7;
            sW[(kq * 4 + 0) * 66 + r] = tf32r(wR[j].x);
            sW[(kq * 4 + 1) * 66 + r] = tf32r(wR[j].y);
            sW[(kq * 4 + 2) * 66 + r] = tf32r(wR[j].z);
            sW[(kq * 4 + 3) * 66 + r] = tf32r(wR[j].w);
        }
        __syncthreads();
        if (c + 1 < NC) loadChunk(c + 1);

#pragma unroll
        for (int kk = 0; kk < 32; kk++) {
            const ulonglong2 a01 = *reinterpret_cast<const ulonglong2*>(&sA[kk * 36 + m0]);
            const ulonglong2 a23 = *reinterpret_cast<const ulonglong2*>(&sA[kk * 36 + m0 + 4]);
            const float2 wv = *reinterpret_cast<const float2*>(&sW[kk * 66 + 2 * ng]);
            const unsigned long long w0 = bcast2_(wv.x);
            const unsigned long long w1 = bcast2_(wv.y);
            acc0[0] = ffma2_(a01.x, w0, acc0[0]);
            acc0[1] = ffma2_(a01.y, w0, acc0[1]);
            acc0[2] = ffma2_(a23.x, w0, acc0[2]);
            acc0[3] = ffma2_(a23.y, w0, acc0[3]);
            acc1[0] = ffma2_(a01.x, w1, acc1[0]);
            acc1[1] = ffma2_(a01.y, w1, acc1[1]);
            acc1[2] = ffma2_(a23.x, w1, acc1[2]);
            acc1[3] = ffma2_(a23.y, w1, acc1[3]);
        }
    }

    const int n0 = nbase + 2 * ng;
#pragma unroll
    for (int r = 0; r < 4; r++) {
        float lo, hi;
        const int m = m0 + 2 * r;
        unpack2_(acc0[r], lo, hi);
        dst[(size_t)m * Nout + n0]           = lo;
        dst[(size_t)(m + 1) * Nout + n0]     = hi;
        unpack2_(acc1[r], lo, hi);
        dst[(size_t)m * Nout + n0 + 1]       = lo;
        dst[(size_t)(m + 1) * Nout + n0 + 1] = hi;
    }
}

// ---------------- attention for one batch row (128 threads) ---------------
__device__ __forceinline__ void attn_b(
    int b, int t,
    const float* __restrict__ x, const int* __restrict__ tseq,
    const float* __restrict__ emb, const float* __restrict__ w2,
    const float* __restrict__ b2p, const float* __restrict__ b1,
    float* sh)
{
    float* hw   = sh;            // [1024]
    float* w2s  = sh + 1024;     // [1024]
    float* sc   = sh + 2048;     // [128]
    float* red4 = sh + 2176;     // [4]
    const int tid = threadIdx.x, lane = tid & 31, w = tid >> 5;

    // hW = b1 + sum of 16 hW partials (fixed order)
#pragma unroll
    for (int k = 0; k < 8; k++) {
        const int hh = k * 128 + tid;
        float v = b1[hh];
#pragma unroll
        for (int ks = 0; ks < 16; ks++)
            v += g_part[(size_t)(ks * 32 + b) * H_ + hh];
        hw[hh]  = v;
        w2s[hh] = w2[hh];
    }
    __syncthreads();

    // 128 scores: warp w computes s = j*4 + w
    for (int j = 0; j < 32; j++) {
        const int s = j * 4 + w;
        const float* xw = g_xW + ((size_t)b * S1_ + s) * H_;
        float p = 0.f;
#pragma unroll 8
        for (int i = 0; i < 32; i++) {
            const int hh = i * 32 + lane;
            float v = xw[hh] + hw[hh];
            v = fmaxf(v, 0.f);
            p += v * w2s[hh];
        }
#pragma unroll
        for (int o = 16; o > 0; o >>= 1) p += __shfl_xor_sync(0xffffffffu, p, o);
        if (lane == 0) sc[s] = p + b2p[0];
    }
    __syncthreads();

    // log_softmax over the 128 scores
    const float v0 = sc[tid];
    float mv = v0;
#pragma unroll
    for (int o = 16; o > 0; o >>= 1) mv = fmaxf(mv, __shfl_xor_sync(0xffffffffu, mv, o));
    if (lane == 0) red4[w] = mv;
    __syncthreads();
    const float mx = fmaxf(fmaxf(red4[0], red4[1]), fmaxf(red4[2], red4[3]));
    __syncthreads();
    const float shv = v0 - mx;
    float e = expf(shv);
#pragma unroll
    for (int o = 16; o > 0; o >>= 1) e += __shfl_xor_sync(0xffffffffu, e, o);
    if (lane == 0) red4[w] = e;
    __syncthreads();
    const float lse = logf(red4[0] + red4[1] + red4[2] + red4[3]);
    sc[tid] = shv - lse;          // logw
    __syncthreads();

    // context + emb gather -> inp0
    const int tgt = tseq[b * T_ + t];
#pragma unroll
    for (int k = 0; k < 6; k++) {
        const int e2 = k * 128 + tid;
        const float* xb = x + (size_t)b * S1_ * E_ + e2;
        float ctx = 0.f;
#pragma unroll 8
        for (int s = 0; s < S1_; s++) ctx += sc[s] * xb[(size_t)s * E_];
        g_inp0[b * 2 * E_ + E_ + e2] = ctx;
        g_inp0[b * 2 * E_ + e2]      = emb[(size_t)tgt * E_ + e2];
    }
    __syncthreads();
}

// ---------------- LSTM pointwise: (b, 128-j chunk), 8 partial slices ------
__device__ __forceinline__ void lstm_update_chunk8(int l, int b, int j0)
{
    const int j = j0 + threadIdx.x;
    float gi = g_bsum[l * 4 * H_ + j];
    float gf = g_bsum[l * 4 * H_ + H_ + j];
    float gg = g_bsum[l * 4 * H_ + 2 * H_ + j];
    float go = g_bsum[l * 4 * H_ + 3 * H_ + j];
#pragma unroll
    for (int ks = 0; ks < 8; ks++) {
        const float* p = g_part + (size_t)(ks * 32 + b) * 4 * H_;
        gi += p[j];
        gf += p[H_ + j];
        gg += p[2 * H_ + j];
        go += p[3 * H_ + j];
    }
    float* cp = g_c + (size_t)(l * B_ + b) * H_ + j;
    float* hp = g_h + (size_t)(l * B_ + b) * H_ + j;
    const float si = 1.f / (1.f + expf(-gi));
    const float sf = 1.f / (1.f + expf(-gf));
    const float so = 1.f / (1.f + expf(-go));
    const float cn = sf * (*cp) + si * tanhf(gg);
    *cp = cn;
    *hp = so * tanhf(cn);
}

// ---------------- logits from 4 fc partial slices + log_softmax -----------
__device__ __forceinline__ void ls_row128(float* __restrict__ rowBase,
                                          const float* __restrict__ fcb,
                                          int b, int set, float* red)
{
    float* row = rowBase + (size_t)b * ((long long)T_ * V_);
    const int tid = threadIdx.x;
    const int NV4 = V_ / 4;
    const float* fb = g_fcpart + (size_t)set * 4 * B_ * V_;
    const float4* bb = (const float4*)fcb;
    const float4* p0 = (const float4*)(fb + (size_t)b * V_);
    const float4* p1 = (const float4*)(fb + (size_t)(B_ + b) * V_);
    const float4* p2 = (const float4*)(fb + (size_t)(2 * B_ + b) * V_);
    const float4* p3 = (const float4*)(fb + (size_t)(3 * B_ + b) * V_);
    float4* r4 = (float4*)row;

    float m = -1e30f;
    for (int v = tid; v < NV4; v += 128) {
        const float4 a = bb[v], q0 = p0[v], q1 = p1[v], q2 = p2[v], q3 = p3[v];
        float4 r;
        r.x = a.x + q0.x + q1.x + q2.x + q3.x;
        r.y = a.y + q0.y + q1.y + q2.y + q3.y;
        r.z = a.z + q0.z + q1.z + q2.z + q3.z;
        r.w = a.w + q0.w + q1.w + q2.w + q3.w;
        r4[v] = r;
        m = fmaxf(m, fmaxf(fmaxf(r.x, r.y), fmaxf(r.z, r.w)));
    }
    red[tid] = m; __syncthreads();
    for (int st = 64; st > 0; st >>= 1) {
        if (tid < st) red[tid] = fmaxf(red[tid], red[tid + st]);
        __syncthreads();
    }
    m = red[0];
    __syncthreads();

    float s = 0.f;
    for (int v = tid; v < NV4; v += 128) {
        const float4 r = r4[v];
        s += expf(r.x - m) + expf(r.y - m) + expf(r.z - m) + expf(r.w - m);
    }
    red[tid] = s; __syncthreads();
    for (int st = 64; st > 0; st >>= 1) {
        if (tid < st) red[tid] += red[tid + st];
        __syncthreads();
    }
    const float lse = logf(red[0]);
    __syncthreads();

    for (int v = tid; v < NV4; v += 128) {
        float4 r = r4[v];
        r.x = (r.x - m) - lse;
        r.y = (r.y - m) - lse;
        r.z = (r.z - m) - lse;
        r.w = (r.w - m) - lse;
        r4[v] = r;
    }
}

// ---------------- the persistent mega-kernel ------------------------------
__global__ void __launch_bounds__(128) mega(
    const float* __restrict__ x, const int* __restrict__ tseq,
    const float* __restrict__ emb,
    const float* __restrict__ W1, const float* __restrict__ b1,
    const float* __restrict__ W2, const float* __restrict__ b2,
    const float* __restrict__ fcW, const float* __restrict__ fcb,
    const float* __restrict__ Wih0, const float* __restrict__ Whh0,
    const float* __restrict__ Wih1, const float* __restrict__ Whh1,
    const float* __restrict__ Wih2, const float* __restrict__ Whh2,
    float* __restrict__ out)
{
    __shared__ __align__(16) float sh[2 * SHA_STRIDE + 2 * SHW_STRIDE]; // 6528 f
    __shared__ float red[128];
    __shared__ int sepoch;
    if (threadIdx.x == 0) sepoch = 0;

    float* shA = sh;
    float* shW = sh + 2 * SHA_STRIDE;
    const int NB = (int)gridDim.x;

    float* h0 = g_h;
    float* h1 = g_h + B_ * H_;
    float* h2 = g_h + 2 * B_ * H_;

    // ---- phase: xW precompute (2048 tiles, K=768) ----
    for (int task = blockIdx.x; task < 2048; task += NB) {
        const int z = task >> 4, nx = task & 15;
        gemm_core32(x + (size_t)z * 32 * E_, E_, W1, E_ + H_, 0, E_ / 32, nx * 64,
                    g_xW + (size_t)z * 32 * H_, H_, shA, shW);
    }
    gbar(&sepoch);

    for (int t = 0; t < T_; t++) {
        // ---- P0: fc(t-1) 2000 tiles + hW 256 tiles + ls(t-2) 32 rows ----
        const int nFc   = (t > 0)  ? 2000 : 0;
        const int nLs   = (t >= 2) ? 32   : 0;
        const int fcSet = (t - 1) & 1;
        const int lsSet = (t - 2) & 1;
        for (int task = blockIdx.x; task < nFc + 256 + nLs; task += NB) {
            if (task < nFc) {
                const int slice = task / 500, tile = task - slice * 500;
                gemm_core32(h2, H_, fcW, H_, slice * 256, 8, tile * 64,
                            g_fcpart + (size_t)fcSet * 4 * B_ * V_
                                     + (size_t)slice * B_ * V_,
                            V_, shA, shW);
            } else if (task < nFc + 256) {
                const int k = task - nFc;
                const int slice = k & 15, tile = k >> 4;
                gemm_core32(h2, H_, W1 + E_, E_ + H_, slice * 64, 2, tile * 64,
                            g_part + (size_t)slice * 32 * H_, H_, shA, shW);
            } else {
                ls_row128(out + (size_t)(t - 2) * V_, fcb,
                          task - nFc - 256, lsSet, red);
            }
        }
        gbar(&sepoch);

        // ---- P1: attention (32 per-batch tasks) ----
        for (int task = blockIdx.x; task < 32; task += NB)
            attn_b(task, t, x, tseq, emb, W2, b2, b1, sh);
        gbar(&sepoch);

        // ---- layers ----
        for (int l = 0; l < 3; l++) {
            const float* Ain = (l == 0) ? g_inp0 : (l == 1 ? h0 : h1);
            const int    ldA = (l == 0) ? 2 * E_ : H_;
            const float* WA  = (l == 0) ? Wih0 : (l == 1 ? Wih1 : Wih2);
            const int    KsA = (l == 0) ? 384 : 256;
            const float* Bin = (l == 0) ? h0 : (l == 1 ? h1 : h2);
            const float* WB  = (l == 0) ? Whh0 : (l == 1 ? Whh1 : Whh2);

            for (int task = blockIdx.x; task < 512; task += NB) {
                const int slice = task & 7, tile = task >> 3;
                if (slice < 4)
                    gemm_core32(Ain, ldA, WA, ldA, slice * KsA, KsA >> 5, tile * 64,
                                g_part + (size_t)slice * 32 * 4 * H_, 4 * H_, shA, shW);
                else
                    gemm_core32(Bin, H_, WB, H_, (slice - 4) * 256, 8, tile * 64,
                                g_part + (size_t)slice * 32 * 4 * H_, 4 * H_, shA, shW);
            }
            gbar(&sepoch);

            for (int task = blockIdx.x; task < 256; task += NB)
                lstm_update_chunk8(l, task >> 3, (task & 7) * 128);
            gbar(&sepoch);
        }
    }

    // ---- tail: fc(T-1) + ls(T-2), then ls(T-1) ----
    {
        const int fcSet = (T_ - 1) & 1;
        for (int task = blockIdx.x; task < 2000 + 32; task += NB) {
            if (task < 2000) {
                const int slice = task / 500, tile = task - slice * 500;
                gemm_core32(h2, H_, fcW, H_, slice * 256, 8, tile * 64,
                            g_fcpart + (size_t)fcSet * 4 * B_ * V_
                                     + (size_t)slice * B_ * V_,
                            V_, shA, shW);
            } else {
                ls_row128(out + (size_t)(T_ - 2) * V_, fcb,
                          task - 2000, (T_ - 2) & 1, red);
            }
        }
        gbar(&sepoch);
        for (int task = blockIdx.x; task < 32; task += NB)
            ls_row128(out + (size_t)(T_ - 1) * V_, fcb, task, fcSet, red);
    }
}

// ---------------- init kernels ----------------
__global__ void zero_state()
{
    const int idx = blockIdx.x * 1024 + threadIdx.x;
    if (idx < 3 * B_ * H_) { g_h[idx] = 0.f; g_c[idx] = 0.f; }
    if (idx == 0) { g_barCnt = 0; g_barRel = 0; }
}
__global__ void bias_sum(const float* bi0, const float* bh0,
                         const float* bi1, const float* bh1,
                         const float* bi2, const float* bh2)
{
    const int i = blockIdx.x * 1024 + threadIdx.x;
    if (i < 4 * H_) {
        g_bsum[i]          = bi0[i] + bh0[i];
        g_bsum[4 * H_ + i] = bi1[i] + bh1[i];
        g_bsum[8 * H_ + i] = bi2[i] + bh2[i];
    }
}

// ---------------- launch ----------------
extern "C" void kernel_launch(void* const* d_in, const int* in_sizes, int n_in,
                              void* d_out, int out_size)
{
    const float* x    = (const float*)d_in[0];
    const int*   tseq = (const int*)  d_in[1];
    const float* emb  = (const float*)d_in[2];
    const float* W1   = (const float*)d_in[3];   // (H, E+H)
    const float* b1   = (const float*)d_in[4];
    const float* W2   = (const float*)d_in[5];   // (1, H)
    const float* b2   = (const float*)d_in[6];

    const float *fcW, *fcb;
    const float *Wih[3], *Whh[3], *bih[3], *bhh[3];
    int base;
    if (in_sizes[7] == V_ * H_) {          // dict order (expected)
        fcW = (const float*)d_in[7];
        fcb = (const float*)d_in[8];
        base = 9;
    } else {                                // signature order (fallback)
        fcW = (const float*)d_in[19];
        fcb = (const float*)d_in[20];
        base = 7;
    }
    for (int l = 0; l < 3; l++) {
        Wih[l] = (const float*)d_in[base + 4 * l + 0];
        Whh[l] = (const float*)d_in[base + 4 * l + 1];
        bih[l] = (const float*)d_in[base + 4 * l + 2];
        bhh[l] = (const float*)d_in[base + 4 * l + 3];
    }
    float* out = (float*)d_out;

    zero_state<<<96, 1024>>>();
    bias_sum<<<4, 1024>>>(bih[0], bhh[0], bih[1], bhh[1], bih[2], bhh[2]);

    // Grid sized to GUARANTEED co-residency (required for the grid barrier).
    int dev = 0;
    cudaGetDevice(&dev);
    int smCount = 0;
    cudaDeviceGetAttribute(&smCount, cudaDevAttrMultiProcessorCount, dev);
    int occ = 0;
    cudaOccupancyMaxActiveBlocksPerMultiprocessor(&occ, mega, 128, 0);
    if (smCount <= 0) smCount = 148;
    if (occ <= 0) occ = 2;
    int NB = smCount * occ;
    if (NB > 2048) NB = 2048;

    mega<<<NB, 128>>>(x, tseq, emb, W1, b1, W2, b2, fcW, fcb,
                      Wih[0], Whh[0], Wih[1], Whh[1], Wih[2], Whh[2], out);
}

// round 15
// speedup vs baseline: 1.1311x; 1.1311x over previous
#include <cuda_runtime.h>
#include <math.h>
#include <stdint.h>

#define B_  32
#define S1_ 128
#define T_  50
#define E_  768
#define H_  1024
#define V_  32000

// ---------------- device scratch (no allocation allowed) ----------------
__device__ float g_xW[B_ * S1_ * H_];        // x @ W1x^T (precomputed once)
__device__ float g_inp0[B_ * 2 * E_];        // [emb_t ; context]
__device__ float g_h[3 * B_ * H_];
__device__ float g_c[3 * B_ * H_];
__device__ float g_bsum[3 * 4 * H_];         // bih + bhh per layer
__device__ float g_partA[4 * B_ * 4 * H_];   // Wih partials (4 slices)
__device__ float g_partB[12 * B_ * 4 * H_];  // Whh partials (3 layers x 4 slices)
__device__ float g_partHW[16 * B_ * H_];     // hW partials (16 slices)
__device__ float g_fcpart[2 * 4 * B_ * V_];  // fc partials, double-buffered
__device__ int   g_cnt[4 * T_];              // spin counters per step

// ---------------- f32x2 packed helpers ----------------
__device__ __forceinline__ unsigned long long ffma2_(unsigned long long a,
                                                     unsigned long long b,
                                                     unsigned long long c) {
    unsigned long long d;
    asm("fma.rn.f32x2 %0, %1, %2, %3;" : "=l"(d) : "l"(a), "l"(b), "l"(c));
    return d;
}
__device__ __forceinline__ unsigned long long bcast2_(float x) {
    unsigned long long r;
    asm("mov.b64 %0, {%1, %1};" : "=l"(r) : "f"(x));
    return r;
}
__device__ __forceinline__ void unpack2_(unsigned long long v, float& lo, float& hi) {
    asm("mov.b64 {%0, %1}, %2;" : "=f"(lo), "=f"(hi) : "l"(v));
}
__device__ __forceinline__ float tf32r(float x) {
    unsigned u;
    asm("cvt.rna.tf32.f32 %0, %1;" : "=r"(u) : "f"(x));
    return __uint_as_float(u);
}

#define SHA_STRIDE 1152   // 32*36
#define SHW_STRIDE 2112   // 32*66

// ---------------- shared GEMM core: 32 rows x 64 cols, 128 threads --------
// Ping-pong double-buffered smem, one __syncthreads per K-chunk.
__device__ __forceinline__ void gemm_core32(
    const float* __restrict__ A, int ldA,
    const float* __restrict__ W, int ldW,
    int kbase, int NC, int nbase,
    float* __restrict__ dst, int Nout,
    float* shA, float* shW)
{
    const int tid = threadIdx.x;
    const int ng  = tid & 31;
    const int mg  = tid >> 5;
    const int m0  = mg * 8;

    unsigned long long acc0[4], acc1[4];
#pragma unroll
    for (int r = 0; r < 4; r++) { acc0[r] = 0ull; acc1[r] = 0ull; }

    float4 aR[2], wR[4];
    auto loadChunk = [&](int c) {
        const int k0 = kbase + c * 32;
#pragma unroll
        for (int j = 0; j < 2; j++) {
            const int f4 = tid + j * 128;
            const int m  = f4 >> 3, kq = f4 & 7;
            aR[j] = *reinterpret_cast<const float4*>(&A[(size_t)m * ldA + k0 + kq * 4]);
        }
#pragma unroll
        for (int j = 0; j < 4; j++) {
            const int f4 = tid + j * 128;
            const int r  = f4 >> 3, kq = f4 & 7;
            wR[j] = *reinterpret_cast<const float4*>(
                &W[(size_t)(nbase + r) * ldW + k0 + kq * 4]);
        }
    };

    loadChunk(0);
    for (int c = 0; c < NC; c++) {
        float* sA = shA + (c & 1) * SHA_STRIDE;
        float* sW = shW + (c & 1) * SHW_STRIDE;
#pragma unroll
        for (int j = 0; j < 2; j++) {
            const int f4 = tid + j * 128;
            const int m  = f4 >> 3, kq = f4 & 7;
            sA[(kq * 4 + 0) * 36 + m] = tf32r(aR[j].x);
            sA[(kq * 4 + 1) * 36 + m] = tf32r(aR[j].y);
            sA[(kq * 4 + 2) * 36 + m] = tf32r(aR[j].z);
            sA[(kq * 4 + 3) * 36 + m] = tf32r(aR[j].w);
        }
#pragma unroll
        for (int j = 0; j < 4; j++) {
            const int f4 = tid + j * 128;
            const int r  = f4 >> 3, kq = f4 & 7;
            sW[(kq * 4 + 0) * 66 + r] = tf32r(wR[j].x);
            sW[(kq * 4 + 1) * 66 + r] = tf32r(wR[j].y);
            sW[(kq * 4 + 2) * 66 + r] = tf32r(wR[j].z);
            sW[(kq * 4 + 3) * 66 + r] = tf32r(wR[j].w);
        }
        __syncthreads();
        if (c + 1 < NC) loadChunk(c + 1);

#pragma unroll
        for (int kk = 0; kk < 32; kk++) {
            const ulonglong2 a01 = *reinterpret_cast<const ulonglong2*>(&sA[kk * 36 + m0]);
            const ulonglong2 a23 = *reinterpret_cast<const ulonglong2*>(&sA[kk * 36 + m0 + 4]);
            const float2 wv = *reinterpret_cast<const float2*>(&sW[kk * 66 + 2 * ng]);
            const unsigned long long w0 = bcast2_(wv.x);
            const unsigned long long w1 = bcast2_(wv.y);
            acc0[0] = ffma2_(a01.x, w0, acc0[0]);
            acc0[1] = ffma2_(a01.y, w0, acc0[1]);
            acc0[2] = ffma2_(a23.x, w0, acc0[2]);
            acc0[3] = ffma2_(a23.y, w0, acc0[3]);
            acc1[0] = ffma2_(a01.x, w1, acc1[0]);
            acc1[1] = ffma2_(a01.y, w1, acc1[1]);
            acc1[2] = ffma2_(a23.x, w1, acc1[2]);
            acc1[3] = ffma2_(a23.y, w1, acc1[3]);
        }
    }

    const int n0 = nbase + 2 * ng;
#pragma unroll
    for (int r = 0; r < 4; r++) {
        float lo, hi;
        const int m = m0 + 2 * r;
        unpack2_(acc0[r], lo, hi);
        dst[(size_t)m * Nout + n0]           = lo;
        dst[(size_t)(m + 1) * Nout + n0]     = hi;
        unpack2_(acc1[r], lo, hi);
        dst[(size_t)m * Nout + n0 + 1]       = lo;
        dst[(size_t)(m + 1) * Nout + n0 + 1] = hi;
    }
}

// ---------------- attention for one batch row (128 threads) ---------------
__device__ __forceinline__ void attn_b(
    int b, int t,
    const float* __restrict__ x, const int* __restrict__ tseq,
    const float* __restrict__ emb, const float* __restrict__ w2,
    const float* __restrict__ b2p, const float* __restrict__ b1,
    float* sh)
{
    float* hw   = sh;            // [1024]
    float* w2s  = sh + 1024;     // [1024]
    float* sc   = sh + 2048;     // [128]
    float* red4 = sh + 2176;     // [4]
    const int tid = threadIdx.x, lane = tid & 31, w = tid >> 5;

    // hW = b1 + sum of 16 hW partials (fixed order)
#pragma unroll
    for (int k = 0; k < 8; k++) {
        const int hh = k * 128 + tid;
        float v = b1[hh];
#pragma unroll
        for (int ks = 0; ks < 16; ks++)
            v += g_partHW[(size_t)(ks * 32 + b) * H_ + hh];
        hw[hh]  = v;
        w2s[hh] = w2[hh];
    }
    __syncthreads();

    // 128 scores: warp w computes s = j*4 + w
    for (int j = 0; j < 32; j++) {
        const int s = j * 4 + w;
        const float* xw = g_xW + ((size_t)b * S1_ + s) * H_;
        float p = 0.f;
#pragma unroll 8
        for (int i = 0; i < 32; i++) {
            const int hh = i * 32 + lane;
            float v = xw[hh] + hw[hh];
            v = fmaxf(v, 0.f);
            p += v * w2s[hh];
        }
#pragma unroll
        for (int o = 16; o > 0; o >>= 1) p += __shfl_xor_sync(0xffffffffu, p, o);
        if (lane == 0) sc[s] = p + b2p[0];
    }
    __syncthreads();

    // log_softmax over the 128 scores
    const float v0 = sc[tid];
    float mv = v0;
#pragma unroll
    for (int o = 16; o > 0; o >>= 1) mv = fmaxf(mv, __shfl_xor_sync(0xffffffffu, mv, o));
    if (lane == 0) red4[w] = mv;
    __syncthreads();
    const float mx = fmaxf(fmaxf(red4[0], red4[1]), fmaxf(red4[2], red4[3]));
    __syncthreads();
    const float shv = v0 - mx;
    float e = expf(shv);
#pragma unroll
    for (int o = 16; o > 0; o >>= 1) e += __shfl_xor_sync(0xffffffffu, e, o);
    if (lane == 0) red4[w] = e;
    __syncthreads();
    const float lse = logf(red4[0] + red4[1] + red4[2] + red4[3]);
    sc[tid] = shv - lse;          // logw
    __syncthreads();

    // context + emb gather -> inp0
    const int tgt = tseq[b * T_ + t];
#pragma unroll
    for (int k = 0; k < 6; k++) {
        const int e2 = k * 128 + tid;
        const float* xb = x + (size_t)b * S1_ * E_ + e2;
        float ctx = 0.f;
#pragma unroll 8
        for (int s = 0; s < S1_; s++) ctx += sc[s] * xb[(size_t)s * E_];
        g_inp0[b * 2 * E_ + E_ + e2] = ctx;
        g_inp0[b * 2 * E_ + e2]      = emb[(size_t)tgt * E_ + e2];
    }
}

// ---------------- LSTM pointwise: 4 Wih + 4 Whh partial slices ------------
__device__ __forceinline__ void lstm_update_chunk(int l, int b, int j0)
{
    const int j = j0 + threadIdx.x;
    float gi = g_bsum[l * 4 * H_ + j];
    float gf = g_bsum[l * 4 * H_ + H_ + j];
    float gg = g_bsum[l * 4 * H_ + 2 * H_ + j];
    float go = g_bsum[l * 4 * H_ + 3 * H_ + j];
#pragma unroll
    for (int ks = 0; ks < 4; ks++) {
        const float* p = g_partA + (size_t)(ks * 32 + b) * 4 * H_;
        gi += p[j]; gf += p[H_ + j]; gg += p[2 * H_ + j]; go += p[3 * H_ + j];
    }
#pragma unroll
    for (int ks = 0; ks < 4; ks++) {
        const float* p = g_partB + (size_t)((l * 4 + ks) * 32 + b) * 4 * H_;
        gi += p[j]; gf += p[H_ + j]; gg += p[2 * H_ + j]; go += p[3 * H_ + j];
    }
    float* cp = g_c + (size_t)(l * B_ + b) * H_ + j;
    float* hp = g_h + (size_t)(l * B_ + b) * H_ + j;
    const float si = 1.f / (1.f + expf(-gi));
    const float sf = 1.f / (1.f + expf(-gf));
    const float so = 1.f / (1.f + expf(-go));
    const float cn = sf * (*cp) + si * tanhf(gg);
    *cp = cn;
    *hp = so * tanhf(cn);
}

// ---------------- logits from 4 fc partial slices + log_softmax -----------
__device__ __forceinline__ void ls_row128(float* __restrict__ rowBase,
                                          const float* __restrict__ fcb,
                                          int b, int set, float* red)
{
    float* row = rowBase + (size_t)b * ((long long)T_ * V_);
    const int tid = threadIdx.x;
    const int NV4 = V_ / 4;
    const float* fb = g_fcpart + (size_t)set * 4 * B_ * V_;
    const float4* bb = (const float4*)fcb;
    const float4* p0 = (const float4*)(fb + (size_t)b * V_);
    const float4* p1 = (const float4*)(fb + (size_t)(B_ + b) * V_);
    const float4* p2 = (const float4*)(fb + (size_t)(2 * B_ + b) * V_);
    const float4* p3 = (const float4*)(fb + (size_t)(3 * B_ + b) * V_);
    float4* r4 = (float4*)row;

    float m = -1e30f;
    for (int v = tid; v < NV4; v += 128) {
        const float4 a = bb[v], q0 = p0[v], q1 = p1[v], q2 = p2[v], q3 = p3[v];
        float4 r;
        r.x = a.x + q0.x + q1.x + q2.x + q3.x;
        r.y = a.y + q0.y + q1.y + q2.y + q3.y;
        r.z = a.z + q0.z + q1.z + q2.z + q3.z;
        r.w = a.w + q0.w + q1.w + q2.w + q3.w;
        r4[v] = r;
        m = fmaxf(m, fmaxf(fmaxf(r.x, r.y), fmaxf(r.z, r.w)));
    }
    red[tid] = m; __syncthreads();
    for (int st = 64; st > 0; st >>= 1) {
        if (tid < st) red[tid] = fmaxf(red[tid], red[tid + st]);
        __syncthreads();
    }
    m = red[0];
    __syncthreads();

    float s = 0.f;
    for (int v = tid; v < NV4; v += 128) {
        const float4 r = r4[v];
        s += expf(r.x - m) + expf(r.y - m) + expf(r.z - m) + expf(r.w - m);
    }
    red[tid] = s; __syncthreads();
    for (int st = 64; st > 0; st >>= 1) {
        if (tid < st) red[tid] += red[tid + st];
        __syncthreads();
    }
    const float lse = logf(red[0]);
    __syncthreads();

    for (int v = tid; v < NV4; v += 128) {
        float4 r = r4[v];
        r.x = (r.x - m) - lse;
        r.y = (r.y - m) - lse;
        r.z = (r.z - m) - lse;
        r.w = (r.w - m) - lse;
        r4[v] = r;
    }
}

// ---------------- P0: hW + Whh(all layers) + fc(t-1) + fused attention ----
// bid layout: [0,256) hW | [256,1024) Whh | [1024,1024+nFc) fc | last 32 attn.
// attn spinners are the HIGHEST bids -> scheduled last; they wait only on the
// 256 hW blocks (bids 0..255, wave 1) -> no deadlock.
__global__ void __launch_bounds__(128, 5) p0k(
    const float* __restrict__ x, const int* __restrict__ tseq,
    const float* __restrict__ emb,
    const float* __restrict__ W1, const float* __restrict__ b1,
    const float* __restrict__ w2, const float* __restrict__ b2,
    const float* __restrict__ fcW,
    const float* __restrict__ Wh0, const float* __restrict__ Wh1,
    const float* __restrict__ Wh2,
    int t, int nFc, int fcSet, int* cntHW)
{
    __shared__ __align__(16) float sh[2 * SHA_STRIDE + 2 * SHW_STRIDE];
    float* shA = sh;
    float* shW = sh + 2 * SHA_STRIDE;
    const float* h2 = g_h + 2 * B_ * H_;
    const int bx = blockIdx.x;

    if (bx < 256) {                      // hW partials: 16 slices x 16 tiles
        const int slice = bx & 15, tile = bx >> 4;
        gemm_core32(h2, H_, W1 + E_, E_ + H_, slice * 64, 2, tile * 64,
                    g_partHW + (size_t)slice * B_ * H_, H_, shA, shW);
        __threadfence();
        __syncthreads();
        if (threadIdx.x == 0) atomicAdd(cntHW, 1);
    } else if (bx < 1024) {              // Whh partials: 3 layers x 4 x 64
        const int k = bx - 256;
        const int l = k >> 8, r = k & 255;
        const int slice = r & 3, tile = r >> 2;
        const float* hl = g_h + (size_t)l * B_ * H_;
        const float* W  = (l == 0) ? Wh0 : (l == 1 ? Wh1 : Wh2);
        gemm_core32(hl, H_, W, H_, slice * 256, 8, tile * 64,
                    g_partB + (size_t)(l * 4 + slice) * B_ * 4 * H_, 4 * H_,
                    shA, shW);
    } else if (bx < 1024 + nFc) {        // fc(t-1): 4 slices x 500 tiles
        const int k = bx - 1024;
        const int slice = k / 500, tile = k - slice * 500;
        gemm_core32(h2, H_, fcW, H_, slice * 256, 8, tile * 64,
                    g_fcpart + (size_t)fcSet * 4 * B_ * V_
                             + (size_t)slice * B_ * V_,
                    V_, shA, shW);
    } else {                             // attention spinners (32)
        const int b = bx - 1024 - nFc;
        if (threadIdx.x == 0) {
            while (atomicAdd(cntHW, 0) < 256) __nanosleep(128);
        }
        __syncthreads();
        __threadfence();                 // acquire hW partials
        attn_b(b, t, x, tseq, emb, w2, b2, b1, sh);
    }
}

// ---------------- gW_l: Wih_l partials + spin-fused lstm_pw + optional ls --
// grid: 256 main + 256 spinners (+32 ls). Co-residency guaranteed:
// __launch_bounds__(128,5) -> >=5 blocks/SM -> >=740 resident >= 544.
__global__ void __launch_bounds__(128, 5) gwk(
    const float* __restrict__ A, int ldA, const float* __restrict__ W, int Ks,
    int l, int* cnt,
    float* lsOut, const float* __restrict__ fcb, int lsSet)
{
    __shared__ __align__(16) float sh[2 * SHA_STRIDE + 2 * SHW_STRIDE];
    __shared__ float red[128];
    float* shA = sh;
    float* shW = sh + 2 * SHA_STRIDE;
    const int bx = blockIdx.x;

    if (bx < 256) {                      // Wih_l partials: 4 slices x 64 tiles
        const int slice = bx & 3, tile = bx >> 2;
        gemm_core32(A, ldA, W, ldA, slice * Ks, Ks >> 5, tile * 64,
                    g_partA + (size_t)slice * B_ * 4 * H_, 4 * H_, shA, shW);
        __threadfence();
        __syncthreads();
        if (threadIdx.x == 0) atomicAdd(cnt, 1);
    } else if (bx < 512) {               // lstm pointwise spinners
        const int local = bx - 256;
        if (threadIdx.x == 0) {
            while (atomicAdd(cnt, 0) < 256) __nanosleep(128);
        }
        __syncthreads();
        __threadfence();                 // acquire Wih partials
        lstm_update_chunk(l, local >> 3, (local & 7) * 128);
    } else {                             // log_softmax(t-1): 32 rows
        ls_row128(lsOut, fcb, bx - 512, lsSet, red);
    }
}

// ---------------- xW precompute ----------------
__global__ void __launch_bounds__(128, 5) gemm_xw(const float* __restrict__ x,
                                                  const float* __restrict__ W1)
{
    __shared__ __align__(16) float sh[2 * SHA_STRIDE + 2 * SHW_STRIDE];
    const int z = blockIdx.x >> 4, nx = blockIdx.x & 15;
    gemm_core32(x + (size_t)z * 32 * E_, E_, W1, E_ + H_, 0, E_ / 32, nx * 64,
                g_xW + (size_t)z * 32 * H_, H_, sh, sh + 2 * SHA_STRIDE);
}

// ---------------- tail: fc(T-1) and final ls ----------------
__global__ void __launch_bounds__(128, 5) fc_tail(const float* __restrict__ fcW,
                                                  int fcSet)
{
    __shared__ __align__(16) float sh[2 * SHA_STRIDE + 2 * SHW_STRIDE];
    const float* h2 = g_h + 2 * B_ * H_;
    const int slice = blockIdx.x / 500, tile = blockIdx.x - slice * 500;
    gemm_core32(h2, H_, fcW, H_, slice * 256, 8, tile * 64,
                g_fcpart + (size_t)fcSet * 4 * B_ * V_ + (size_t)slice * B_ * V_,
                V_, sh, sh + 2 * SHA_STRIDE);
}
__global__ void __launch_bounds__(128) ls_tail(float* outBase,
                                               const float* __restrict__ fcb,
                                               int set)
{
    __shared__ float red[128];
    ls_row128(outBase, fcb, blockIdx.x, set, red);
}

// ---------------- init ----------------
__global__ void zero_state()
{
    const int idx = blockIdx.x * 1024 + threadIdx.x;
    if (idx < 3 * B_ * H_) { g_h[idx] = 0.f; g_c[idx] = 0.f; }
    if (idx < 4 * T_) g_cnt[idx] = 0;
}
__global__ void bias_sum(const float* bi0, const float* bh0,
                         const float* bi1, const float* bh1,
                         const float* bi2, const float* bh2)
{
    const int i = blockIdx.x * 1024 + threadIdx.x;
    if (i < 4 * H_) {
        g_bsum[i]          = bi0[i] + bh0[i];
        g_bsum[4 * H_ + i] = bi1[i] + bh1[i];
        g_bsum[8 * H_ + i] = bi2[i] + bh2[i];
    }
}

// ---------------- launch ----------------
extern "C" void kernel_launch(void* const* d_in, const int* in_sizes, int n_in,
                              void* d_out, int out_size)
{
    const float* x    = (const float*)d_in[0];
    const int*   tseq = (const int*)  d_in[1];
    const float* emb  = (const float*)d_in[2];
    const float* W1   = (const float*)d_in[3];   // (H, E+H)
    const float* b1   = (const float*)d_in[4];
    const float* W2   = (const float*)d_in[5];   // (1, H)
    const float* b2   = (const float*)d_in[6];

    const float *fcW, *fcb;
    const float *Wih[3], *Whh[3], *bih[3], *bhh[3];
    int base;
    if (in_sizes[7] == V_ * H_) {          // dict order (expected)
        fcW = (const float*)d_in[7];
        fcb = (const float*)d_in[8];
        base = 9;
    } else {                                // signature order (fallback)
        fcW = (const float*)d_in[19];
        fcb = (const float*)d_in[20];
        base = 7;
    }
    for (int l = 0; l < 3; l++) {
        Wih[l] = (const float*)d_in[base + 4 * l + 0];
        Whh[l] = (const float*)d_in[base + 4 * l + 1];
        bih[l] = (const float*)d_in[base + 4 * l + 2];
        bhh[l] = (const float*)d_in[base + 4 * l + 3];
    }
    float* out = (float*)d_out;

    float *inp0, *h;
    int* cntBase;
    cudaGetSymbolAddress((void**)&inp0,    g_inp0);
    cudaGetSymbolAddress((void**)&h,       g_h);
    cudaGetSymbolAddress((void**)&cntBase, g_cnt);
    float* h0 = h;
    float* h1 = h + B_ * H_;

    zero_state<<<96, 1024>>>();
    bias_sum<<<4, 1024>>>(bih[0], bhh[0], bih[1], bhh[1], bih[2], bhh[2]);
    gemm_xw<<<2048, 128>>>(x, W1);

    for (int t = 0; t < T_; t++) {
        const int nFc   = (t > 0) ? 2000 : 0;
        const int fcSet = (t - 1) & 1;

        // P0: hW + Whh(all) + fc(t-1) + attention spinners
        p0k<<<1024 + nFc + 32, 128>>>(
            x, tseq, emb, W1, b1, W2, b2, fcW,
            Whh[0], Whh[1], Whh[2],
            t, nFc, fcSet, cntBase + t * 4 + 3);

        // gW0 (+lp0, +ls(t-1) when t>=1)
        gwk<<<(t > 0) ? 544 : 512, 128>>>(
            inp0, 2 * E_, Wih[0], 384, 0, cntBase + t * 4 + 0,
            out + (size_t)(t > 0 ? t - 1 : 0) * V_, fcb, fcSet);

        // gW1 (+lp1)
        gwk<<<512, 128>>>(
            h0, H_, Wih[1], 256, 1, cntBase + t * 4 + 1,
            nullptr, fcb, 0);

        // gW2 (+lp2)
        gwk<<<512, 128>>>(
            h1, H_, Wih[2], 256, 2, cntBase + t * 4 + 2,
            nullptr, fcb, 0);
    }

    // tail: fc(T-1), then ls(T-1)
    fc_tail<<<2000, 128>>>(fcW, (T_ - 1) & 1);
    ls_tail<<<B_, 128>>>(out + (size_t)(T_ - 1) * V_, fcb, (T_ - 1) & 1);
}

// round 16
// speedup vs baseline: 1.3025x; 1.1516x over previous
#include <cuda_runtime.h>
#include <math.h>
#include <stdint.h>

#define B_  32
#define S1_ 128
#define T_  50
#define E_  768
#define H_  1024
#define V_  32000

// ---------------- device scratch (no allocation allowed) ----------------
__device__ float g_xW[B_ * S1_ * H_];        // x @ W1x^T (precomputed once)
__device__ float g_inp0[B_ * 2 * E_];        // [emb_t ; context]
__device__ float g_h[3 * B_ * H_];
__device__ float g_c[3 * B_ * H_];
__device__ float g_bsum[3 * 4 * H_];         // bih + bhh per layer
__device__ float g_partA[4 * B_ * 4 * H_];   // gates partials (4 slices)
__device__ float g_partHW[16 * B_ * H_];     // hW partials (16 slices)
__device__ float g_fcpart[2 * 4 * B_ * V_];  // fc partials, double-buffered
__device__ int   g_cnt[3 * T_];              // spin counters (per step, layer)

// ---------------- f32x2 packed helpers ----------------
__device__ __forceinline__ unsigned long long ffma2_(unsigned long long a,
                                                     unsigned long long b,
                                                     unsigned long long c) {
    unsigned long long d;
    asm("fma.rn.f32x2 %0, %1, %2, %3;" : "=l"(d) : "l"(a), "l"(b), "l"(c));
    return d;
}
__device__ __forceinline__ unsigned long long bcast2_(float x) {
    unsigned long long r;
    asm("mov.b64 %0, {%1, %1};" : "=l"(r) : "f"(x));
    return r;
}
__device__ __forceinline__ void unpack2_(unsigned long long v, float& lo, float& hi) {
    asm("mov.b64 {%0, %1}, %2;" : "=f"(lo), "=f"(hi) : "l"(v));
}
__device__ __forceinline__ float tf32r(float x) {
    unsigned u;
    asm("cvt.rna.tf32.f32 %0, %1;" : "=r"(u) : "f"(x));
    return __uint_as_float(u);
}

// ---------------- PDL helpers ----------------
__device__ __forceinline__ void pdl_wait()    { asm volatile("griddepcontrol.wait;" ::: "memory"); }
__device__ __forceinline__ void pdl_trigger() { asm volatile("griddepcontrol.launch_dependents;" ::: "memory"); }

// ---------------- shared GEMM core: 32 rows x 64 cols, 128 threads --------
// SINGLE-buffer smem (13KB — residency-friendly; R12/R13 showed ping-pong
// halves residency and regresses). Reg-prefetch of next chunk hides LDG.
__device__ __forceinline__ void gemm_core32(
    const float* __restrict__ A, int ldA,
    const float* __restrict__ W, int ldW,
    int kbase, int NC, int nbase,
    float* __restrict__ dst, int Nout,
    float* shA, float* shW)
{
    const int tid = threadIdx.x;
    const int ng  = tid & 31;
    const int mg  = tid >> 5;
    const int m0  = mg * 8;

    unsigned long long acc0[4], acc1[4];
#pragma unroll
    for (int r = 0; r < 4; r++) { acc0[r] = 0ull; acc1[r] = 0ull; }

    float4 aR[2], wR[4];
    auto loadChunk = [&](int c) {
        const int k0 = kbase + c * 32;
#pragma unroll
        for (int j = 0; j < 2; j++) {
            const int f4 = tid + j * 128;
            const int m  = f4 >> 3, kq = f4 & 7;
            aR[j] = *reinterpret_cast<const float4*>(&A[(size_t)m * ldA + k0 + kq * 4]);
        }
#pragma unroll
        for (int j = 0; j < 4; j++) {
            const int f4 = tid + j * 128;
            const int r  = f4 >> 3, kq = f4 & 7;
            wR[j] = *reinterpret_cast<const float4*>(
                &W[(size_t)(nbase + r) * ldW + k0 + kq * 4]);
        }
    };

    loadChunk(0);
    for (int c = 0; c < NC; c++) {
        __syncthreads();
#pragma unroll
        for (int j = 0; j < 2; j++) {
            const int f4 = tid + j * 128;
            const int m  = f4 >> 3, kq = f4 & 7;
            shA[(kq * 4 + 0) * 36 + m] = tf32r(aR[j].x);
            shA[(kq * 4 + 1) * 36 + m] = tf32r(aR[j].y);
            shA[(kq * 4 + 2) * 36 + m] = tf32r(aR[j].z);
            shA[(kq * 4 + 3) * 36 + m] = tf32r(aR[j].w);
        }
#pragma unroll
        for (int j = 0; j < 4; j++) {
            const int f4 = tid + j * 128;
            const int r  = f4 >> 3, kq = f4 & 7;
            shW[(kq * 4 + 0) * 66 + r] = tf32r(wR[j].x);
            shW[(kq * 4 + 1) * 66 + r] = tf32r(wR[j].y);
            shW[(kq * 4 + 2) * 66 + r] = tf32r(wR[j].z);
            shW[(kq * 4 + 3) * 66 + r] = tf32r(wR[j].w);
        }
        __syncthreads();
        if (c + 1 < NC) loadChunk(c + 1);

#pragma unroll
        for (int kk = 0; kk < 32; kk++) {
            const ulonglong2 a01 = *reinterpret_cast<const ulonglong2*>(&shA[kk * 36 + m0]);
            const ulonglong2 a23 = *reinterpret_cast<const ulonglong2*>(&shA[kk * 36 + m0 + 4]);
            const float2 wv = *reinterpret_cast<const float2*>(&shW[kk * 66 + 2 * ng]);
            const unsigned long long w0 = bcast2_(wv.x);
            const unsigned long long w1 = bcast2_(wv.y);
            acc0[0] = ffma2_(a01.x, w0, acc0[0]);
            acc0[1] = ffma2_(a01.y, w0, acc0[1]);
            acc0[2] = ffma2_(a23.x, w0, acc0[2]);
            acc0[3] = ffma2_(a23.y, w0, acc0[3]);
            acc1[0] = ffma2_(a01.x, w1, acc1[0]);
            acc1[1] = ffma2_(a01.y, w1, acc1[1]);
            acc1[2] = ffma2_(a23.x, w1, acc1[2]);
            acc1[3] = ffma2_(a23.y, w1, acc1[3]);
        }
    }

    const int n0 = nbase + 2 * ng;
#pragma unroll
    for (int r = 0; r < 4; r++) {
        float lo, hi;
        const int m = m0 + 2 * r;
        unpack2_(acc0[r], lo, hi);
        dst[(size_t)m * Nout + n0]           = lo;
        dst[(size_t)(m + 1) * Nout + n0]     = hi;
        unpack2_(acc1[r], lo, hi);
        dst[(size_t)m * Nout + n0 + 1]       = lo;
        dst[(size_t)(m + 1) * Nout + n0 + 1] = hi;
    }
}

// ---------------- LSTM pointwise: 4 gates partial slices ------------------
__device__ __forceinline__ void lstm_update_chunk(int l, int b, int j0)
{
    const int j = j0 + threadIdx.x;
    float gi = g_bsum[l * 4 * H_ + j];
    float gf = g_bsum[l * 4 * H_ + H_ + j];
    float gg = g_bsum[l * 4 * H_ + 2 * H_ + j];
    float go = g_bsum[l * 4 * H_ + 3 * H_ + j];
#pragma unroll
    for (int ks = 0; ks < 4; ks++) {
        const float* p = g_partA + (size_t)(ks * 32 + b) * 4 * H_;
        gi += p[j]; gf += p[H_ + j]; gg += p[2 * H_ + j]; go += p[3 * H_ + j];
    }
    float* cp = g_c + (size_t)(l * B_ + b) * H_ + j;
    float* hp = g_h + (size_t)(l * B_ + b) * H_ + j;
    const float si = 1.f / (1.f + expf(-gi));
    const float sf = 1.f / (1.f + expf(-gf));
    const float so = 1.f / (1.f + expf(-go));
    const float cn = sf * (*cp) + si * tanhf(gg);
    *cp = cn;
    *hp = so * tanhf(cn);
}

// ---------------- logits from 4 fc partial slices + log_softmax -----------
__device__ __forceinline__ void ls_row128(float* __restrict__ rowBase,
                                          const float* __restrict__ fcb,
                                          int b, int set, float* red)
{
    float* row = rowBase + (size_t)b * ((long long)T_ * V_);
    const int tid = threadIdx.x;
    const int NV4 = V_ / 4;
    const float* fb = g_fcpart + (size_t)set * 4 * B_ * V_;
    const float4* bb = (const float4*)fcb;
    const float4* p0 = (const float4*)(fb + (size_t)b * V_);
    const float4* p1 = (const float4*)(fb + (size_t)(B_ + b) * V_);
    const float4* p2 = (const float4*)(fb + (size_t)(2 * B_ + b) * V_);
    const float4* p3 = (const float4*)(fb + (size_t)(3 * B_ + b) * V_);
    float4* r4 = (float4*)row;

    float m = -1e30f;
    for (int v = tid; v < NV4; v += 128) {
        const float4 a = bb[v], q0 = p0[v], q1 = p1[v], q2 = p2[v], q3 = p3[v];
        float4 r;
        r.x = a.x + q0.x + q1.x + q2.x + q3.x;
        r.y = a.y + q0.y + q1.y + q2.y + q3.y;
        r.z = a.z + q0.z + q1.z + q2.z + q3.z;
        r.w = a.w + q0.w + q1.w + q2.w + q3.w;
        r4[v] = r;
        m = fmaxf(m, fmaxf(fmaxf(r.x, r.y), fmaxf(r.z, r.w)));
    }
    red[tid] = m; __syncthreads();
    for (int st = 64; st > 0; st >>= 1) {
        if (tid < st) red[tid] = fmaxf(red[tid], red[tid + st]);
        __syncthreads();
    }
    m = red[0];
    __syncthreads();

    float s = 0.f;
    for (int v = tid; v < NV4; v += 128) {
        const float4 r = r4[v];
        s += expf(r.x - m) + expf(r.y - m) + expf(r.z - m) + expf(r.w - m);
    }
    red[tid] = s; __syncthreads();
    for (int st = 64; st > 0; st >>= 1) {
        if (tid < st) red[tid] += red[tid + st];
        __syncthreads();
    }
    const float lse = logf(red[0]);
    __syncthreads();

    for (int v = tid; v < NV4; v += 128) {
        float4 r = r4[v];
        r.x = (r.x - m) - lse;
        r.y = (r.y - m) - lse;
        r.z = (r.z - m) - lse;
        r.w = (r.w - m) - lse;
        r4[v] = r;
    }
}

// ---------------- P0: hW + fc(t-1) + ls(t-2) (no spinners) ---------------
__global__ void __launch_bounds__(128) p0k(
    const float* __restrict__ W1, const float* __restrict__ fcW,
    const float* __restrict__ fcb, float* lsOut,
    int nFc, int fcSet, int lsSet)
{
    __shared__ __align__(16) float shA[32 * 36];
    __shared__ __align__(16) float shW[32 * 66];
    __shared__ float red[128];
    const int bx = blockIdx.x;
    const float* h2 = g_h + 2 * B_ * H_;

    pdl_wait();

    if (bx < 256) {                      // hW partials: 16 slices x 16 tiles
        const int slice = bx & 15, tile = bx >> 4;
        gemm_core32(h2, H_, W1 + E_, E_ + H_, slice * 64, 2, tile * 64,
                    g_partHW + (size_t)slice * B_ * H_, H_, shA, shW);
    } else if (bx < 256 + nFc) {         // fc(t-1): 4 slices x 500 tiles
        const int k = bx - 256;
        const int slice = k / 500, tile = k - slice * 500;
        gemm_core32(h2, H_, fcW, H_, slice * 256, 8, tile * 64,
                    g_fcpart + (size_t)fcSet * 4 * B_ * V_
                             + (size_t)slice * B_ * V_,
                    V_, shA, shW);
    } else {                             // ls(t-2): 32 rows
        ls_row128(lsOut, fcb, bx - 256 - nFc, lsSet, red);
    }
    pdl_trigger();
}

// ---------------- fused attention (R11 form): 32 blocks x 1024 -----------
__global__ void __launch_bounds__(1024) attn_all(
    const float* __restrict__ x, const int* __restrict__ tseq,
    const float* __restrict__ emb, const float* __restrict__ w2,
    const float* __restrict__ b2p, const float* __restrict__ b1, int t)
{
    const int b = blockIdx.x, tid = threadIdx.x;
    __shared__ float hw[H_];
    __shared__ float w2s[H_];
    __shared__ float sc[S1_];
    __shared__ float red4[4];

    pdl_wait();

    {   // hW = b1 + sum of 16 partials
        float v = b1[tid];
#pragma unroll
        for (int ks = 0; ks < 16; ks++)
            v += g_partHW[(size_t)(ks * 32 + b) * H_ + tid];
        hw[tid]  = v;
        w2s[tid] = w2[tid];
    }
    __syncthreads();

    const int lane = tid & 31, w = tid >> 5;
#pragma unroll
    for (int r = 0; r < 4; r++) {
        const int s = r * 32 + w;
        const float* xw = g_xW + ((size_t)b * S1_ + s) * H_;
        float p = 0.f;
#pragma unroll 8
        for (int i = 0; i < 32; i++) {
            const int hh = i * 32 + lane;
            float v = xw[hh] + hw[hh];
            v = fmaxf(v, 0.f);
            p += v * w2s[hh];
        }
#pragma unroll
        for (int o = 16; o > 0; o >>= 1) p += __shfl_xor_sync(0xffffffffu, p, o);
        if (lane == 0) sc[s] = p + b2p[0];
    }
    __syncthreads();

    if (tid < 128) {
        float v = sc[tid];
#pragma unroll
        for (int o = 16; o > 0; o >>= 1) v = fmaxf(v, __shfl_xor_sync(0xffffffffu, v, o));
        if (lane == 0) red4[w] = v;
    }
    __syncthreads();
    const float mx = fmaxf(fmaxf(red4[0], red4[1]), fmaxf(red4[2], red4[3]));
    __syncthreads();
    if (tid < 128) {
        const float sh = sc[tid] - mx;
        sc[tid] = sh;
        float e = expf(sh);
#pragma unroll
        for (int o = 16; o > 0; o >>= 1) e += __shfl_xor_sync(0xffffffffu, e, o);
        if (lane == 0) red4[w] = e;
    }
    __syncthreads();
    const float lse = logf(red4[0] + red4[1] + red4[2] + red4[3]);
    __syncthreads();
    if (tid < 128) sc[tid] -= lse;       // logw
    __syncthreads();

    if (tid < E_) {
        const float* xb = x + (size_t)b * S1_ * E_ + tid;
        float ctx = 0.f;
#pragma unroll 8
        for (int s = 0; s < S1_; s++) ctx += sc[s] * xb[(size_t)s * E_];
        g_inp0[b * 2 * E_ + E_ + tid] = ctx;
        const int tgt = tseq[b * T_ + t];
        g_inp0[b * 2 * E_ + tid] = emb[(size_t)tgt * E_ + tid];
    }
    pdl_trigger();
}

// ---------------- gwk: gates (4 slices x 64 tiles) + spin-fused lp --------
// grid 512; __launch_bounds__(128,5) -> >=740 resident >= 512 (co-residency
// guaranteed, spinners at highest bids).
__global__ void __launch_bounds__(128, 5) gwk(
    const float* __restrict__ A1, int ld1, const float* __restrict__ Wi,
    const float* __restrict__ A2, const float* __restrict__ Wh,
    int l, int* cnt)
{
    __shared__ __align__(16) float shA[32 * 36];
    __shared__ __align__(16) float shW[32 * 66];
    const int bx = blockIdx.x;

    pdl_wait();

    if (bx < 256) {
        const int slice = bx & 3, tile = bx >> 2;
        const int KA = ld1 / 2;          // segA slice length (768 or 512)
        if (slice < 2) {
            gemm_core32(A1, ld1, Wi, ld1, slice * KA, KA >> 5, tile * 64,
                        g_partA + (size_t)slice * B_ * 4 * H_, 4 * H_, shA, shW);
        } else {
            gemm_core32(A2, H_, Wh, H_, (slice - 2) * 512, 16, tile * 64,
                        g_partA + (size_t)slice * B_ * 4 * H_, 4 * H_, shA, shW);
        }
        __threadfence();
        __syncthreads();
        if (threadIdx.x == 0) atomicAdd(cnt, 1);
    } else {
        const int local = bx - 256;
        if (threadIdx.x == 0) {
            while (atomicAdd(cnt, 0) < 256) __nanosleep(128);
        }
        __syncthreads();
        __threadfence();                 // acquire partials
        lstm_update_chunk(l, local >> 3, (local & 7) * 128);
    }
    pdl_trigger();
}

// ---------------- xW precompute ----------------
__global__ void __launch_bounds__(128) gemm_xw(const float* __restrict__ x,
                                               const float* __restrict__ W1)
{
    __shared__ __align__(16) float shA[32 * 36];
    __shared__ __align__(16) float shW[32 * 66];
    const int z = blockIdx.x >> 4, nx = blockIdx.x & 15;
    gemm_core32(x + (size_t)z * 32 * E_, E_, W1, E_ + H_, 0, E_ / 32, nx * 64,
                g_xW + (size_t)z * 32 * H_, H_, shA, shW);
}

// ---------------- tail: fc(T-1) + ls(T-2), then ls(T-1) -------------------
__global__ void __launch_bounds__(128) fc_tail(
    const float* __restrict__ fcW, const float* __restrict__ fcb,
    float* lsOut, int fcSet, int lsSet)
{
    __shared__ __align__(16) float shA[32 * 36];
    __shared__ __align__(16) float shW[32 * 66];
    __shared__ float red[128];
    pdl_wait();
    const float* h2 = g_h + 2 * B_ * H_;
    if (blockIdx.x < 2000) {
        const int slice = blockIdx.x / 500, tile = blockIdx.x - slice * 500;
        gemm_core32(h2, H_, fcW, H_, slice * 256, 8, tile * 64,
                    g_fcpart + (size_t)fcSet * 4 * B_ * V_ + (size_t)slice * B_ * V_,
                    V_, shA, shW);
    } else {
        ls_row128(lsOut, fcb, blockIdx.x - 2000, lsSet, red);
    }
    pdl_trigger();
}
__global__ void __launch_bounds__(128) ls_tail(float* outBase,
                                               const float* __restrict__ fcb,
                                               int set)
{
    __shared__ float red[128];
    pdl_wait();
    ls_row128(outBase, fcb, blockIdx.x, set, red);
}

// ---------------- init ----------------
__global__ void zero_state()
{
    const int idx = blockIdx.x * 1024 + threadIdx.x;
    if (idx < 3 * B_ * H_) { g_h[idx] = 0.f; g_c[idx] = 0.f; }
    if (idx < 3 * T_) g_cnt[idx] = 0;
}
__global__ void bias_sum(const float* bi0, const float* bh0,
                         const float* bi1, const float* bh1,
                         const float* bi2, const float* bh2)
{
    const int i = blockIdx.x * 1024 + threadIdx.x;
    if (i < 4 * H_) {
        g_bsum[i]          = bi0[i] + bh0[i];
        g_bsum[4 * H_ + i] = bi1[i] + bh1[i];
        g_bsum[8 * H_ + i] = bi2[i] + bh2[i];
    }
}

// ---------------- launch ----------------
extern "C" void kernel_launch(void* const* d_in, const int* in_sizes, int n_in,
                              void* d_out, int out_size)
{
    const float* x    = (const float*)d_in[0];
    const int*   tseq = (const int*)  d_in[1];
    const float* emb  = (const float*)d_in[2];
    const float* W1   = (const float*)d_in[3];   // (H, E+H)
    const float* b1   = (const float*)d_in[4];
    const float* W2   = (const float*)d_in[5];   // (1, H)
    const float* b2   = (const float*)d_in[6];

    const float *fcW, *fcb;
    const float *Wih[3], *Whh[3], *bih[3], *bhh[3];
    int base;
    if (in_sizes[7] == V_ * H_) {          // dict order (expected)
        fcW = (const float*)d_in[7];
        fcb = (const float*)d_in[8];
        base = 9;
    } else {                                // signature order (fallback)
        fcW = (const float*)d_in[19];
        fcb = (const float*)d_in[20];
        base = 7;
    }
    for (int l = 0; l < 3; l++) {
        Wih[l] = (const float*)d_in[base + 4 * l + 0];
        Whh[l] = (const float*)d_in[base + 4 * l + 1];
        bih[l] = (const float*)d_in[base + 4 * l + 2];
        bhh[l] = (const float*)d_in[base + 4 * l + 3];
    }
    float* out = (float*)d_out;

    float *inp0, *h;
    int* cntBase;
    cudaGetSymbolAddress((void**)&inp0,    g_inp0);
    cudaGetSymbolAddress((void**)&h,       g_h);
    cudaGetSymbolAddress((void**)&cntBase, g_cnt);
    float* h0 = h;
    float* h1 = h + B_ * H_;

    zero_state<<<96, 1024>>>();
    bias_sum<<<4, 1024>>>(bih[0], bhh[0], bih[1], bhh[1], bih[2], bhh[2]);
    gemm_xw<<<2048, 128>>>(x, W1);

    // PDL launch config (Programmatic Stream Serialization)
    cudaLaunchAttribute pdlAttr[1];
    pdlAttr[0].id = cudaLaunchAttributeProgrammaticStreamSerialization;
    pdlAttr[0].val.programmaticStreamSerializationAllowed = 1;

    auto mkCfg = [&](unsigned grid, unsigned block) {
        cudaLaunchConfig_t cfg = {};
        cfg.gridDim  = dim3(grid, 1, 1);
        cfg.blockDim = dim3(block, 1, 1);
        cfg.dynamicSmemBytes = 0;
        cfg.stream = 0;
        cfg.attrs = pdlAttr;
        cfg.numAttrs = 1;
        return cfg;
    };

    for (int t = 0; t < T_; t++) {
        const int nFc   = (t > 0)  ? 2000 : 0;
        const int nLs   = (t >= 2) ? 32   : 0;
        const int fcSet = (t - 1) & 1;
        const int lsSet = (t - 2) & 1;
        float* lsOut = (t >= 2) ? (out + (size_t)(t - 2) * V_) : out;

        {   // P0: hW + fc(t-1) + ls(t-2)
            cudaLaunchConfig_t cfg = mkCfg(256 + nFc + nLs, 128);
            cudaLaunchKernelEx(&cfg, p0k, W1, fcW, fcb, lsOut, nFc, fcSet, lsSet);
        }
        {   // attention
            cudaLaunchConfig_t cfg = mkCfg(B_, 1024);
            cudaLaunchKernelEx(&cfg, attn_all, x, tseq, emb, W2, b2, b1, t);
        }
        {   // layer 0: inp0@Wih0 (2x768) + h0@Whh0 (2x512) + lp0 spinners
            cudaLaunchConfig_t cfg = mkCfg(512, 128);
            cudaLaunchKernelEx(&cfg, gwk, (const float*)inp0, 2 * E_, Wih[0],
                               (const float*)h0, Whh[0], 0, cntBase + t * 3 + 0);
        }
        {   // layer 1
            cudaLaunchConfig_t cfg = mkCfg(512, 128);
            cudaLaunchKernelEx(&cfg, gwk, (const float*)h0, H_, Wih[1],
                               (const float*)h1, Whh[1], 1, cntBase + t * 3 + 1);
        }
        {   // layer 2
            cudaLaunchConfig_t cfg = mkCfg(512, 128);
            cudaLaunchKernelEx(&cfg, gwk, (const float*)h1, H_, Wih[2],
                               (const float*)(h + 2 * B_ * H_), Whh[2], 2,
                               cntBase + t * 3 + 2);
        }
    }

    // tail: fc(T-1) + ls(T-2), then ls(T-1)
    {
        cudaLaunchConfig_t cfg = mkCfg(2032, 128);
        cudaLaunchKernelEx(&cfg, fc_tail, fcW, fcb,
                           out + (size_t)(T_ - 2) * V_,
                           (T_ - 1) & 1, (T_ - 2) & 1);
    }
    {
        cudaLaunchConfig_t cfg = mkCfg(B_, 128);
        cudaLaunchKernelEx(&cfg, ls_tail, out + (size_t)(T_ - 1) * V_, fcb,
                           (T_ - 1) & 1);
    }
}

// round 17
// speedup vs baseline: 1.6047x; 1.2320x over previous
#include <cuda_runtime.h>
#include <math.h>
#include <stdint.h>

#define B_  32
#define S1_ 128
#define T_  50
#define E_  768
#define H_  1024
#define V_  32000

// ---------------- device scratch (no allocation allowed) ----------------
__device__ float g_xW[B_ * S1_ * H_];        // x @ W1x^T (precomputed once)
__device__ float g_inp0[B_ * 2 * E_];        // [emb_t ; context]
__device__ float g_h[3 * B_ * H_];
__device__ float g_c[3 * B_ * H_];
__device__ float g_bsum[3 * 4 * H_];         // bih + bhh per layer
__device__ float g_part[16 * B_ * 4 * H_];   // gates partials (16 slices)
__device__ float g_partHW[16 * B_ * H_];     // hW partials (16 slices)
__device__ float g_fcpart[2 * 4 * B_ * V_];  // fc partials, double-buffered
__device__ int   g_cnt[3 * T_];              // spin counters (per step, layer)

// ---------------- f32x2 packed helpers ----------------
__device__ __forceinline__ unsigned long long ffma2_(unsigned long long a,
                                                     unsigned long long b,
                                                     unsigned long long c) {
    unsigned long long d;
    asm("fma.rn.f32x2 %0, %1, %2, %3;" : "=l"(d) : "l"(a), "l"(b), "l"(c));
    return d;
}
__device__ __forceinline__ unsigned long long bcast2_(float x) {
    unsigned long long r;
    asm("mov.b64 %0, {%1, %1};" : "=l"(r) : "f"(x));
    return r;
}
__device__ __forceinline__ void unpack2_(unsigned long long v, float& lo, float& hi) {
    asm("mov.b64 {%0, %1}, %2;" : "=f"(lo), "=f"(hi) : "l"(v));
}
__device__ __forceinline__ float tf32r(float x) {
    unsigned u;
    asm("cvt.rna.tf32.f32 %0, %1;" : "=r"(u) : "f"(x));
    return __uint_as_float(u);
}

// ---------------- PDL helpers ----------------
__device__ __forceinline__ void pdl_wait()    { asm volatile("griddepcontrol.wait;" ::: "memory"); }
__device__ __forceinline__ void pdl_trigger() { asm volatile("griddepcontrol.launch_dependents;" ::: "memory"); }

// ---------------- shared GEMM core: 32 rows x 64 cols, 128 threads --------
// SINGLE-buffer smem (13KB), reg-prefetch of next chunk. Shallow NC only!
__device__ __forceinline__ void gemm_core32(
    const float* __restrict__ A, int ldA,
    const float* __restrict__ W, int ldW,
    int kbase, int NC, int nbase,
    float* __restrict__ dst, int Nout,
    float* shA, float* shW)
{
    const int tid = threadIdx.x;
    const int ng  = tid & 31;
    const int mg  = tid >> 5;
    const int m0  = mg * 8;

    unsigned long long acc0[4], acc1[4];
#pragma unroll
    for (int r = 0; r < 4; r++) { acc0[r] = 0ull; acc1[r] = 0ull; }

    float4 aR[2], wR[4];
    auto loadChunk = [&](int c) {
        const int k0 = kbase + c * 32;
#pragma unroll
        for (int j = 0; j < 2; j++) {
            const int f4 = tid + j * 128;
            const int m  = f4 >> 3, kq = f4 & 7;
            aR[j] = *reinterpret_cast<const float4*>(&A[(size_t)m * ldA + k0 + kq * 4]);
        }
#pragma unroll
        for (int j = 0; j < 4; j++) {
            const int f4 = tid + j * 128;
            const int r  = f4 >> 3, kq = f4 & 7;
            wR[j] = *reinterpret_cast<const float4*>(
                &W[(size_t)(nbase + r) * ldW + k0 + kq * 4]);
        }
    };

    loadChunk(0);
    for (int c = 0; c < NC; c++) {
        __syncthreads();
#pragma unroll
        for (int j = 0; j < 2; j++) {
            const int f4 = tid + j * 128;
            const int m  = f4 >> 3, kq = f4 & 7;
            shA[(kq * 4 + 0) * 36 + m] = tf32r(aR[j].x);
            shA[(kq * 4 + 1) * 36 + m] = tf32r(aR[j].y);
            shA[(kq * 4 + 2) * 36 + m] = tf32r(aR[j].z);
            shA[(kq * 4 + 3) * 36 + m] = tf32r(aR[j].w);
        }
#pragma unroll
        for (int j = 0; j < 4; j++) {
            const int f4 = tid + j * 128;
            const int r  = f4 >> 3, kq = f4 & 7;
            shW[(kq * 4 + 0) * 66 + r] = tf32r(wR[j].x);
            shW[(kq * 4 + 1) * 66 + r] = tf32r(wR[j].y);
            shW[(kq * 4 + 2) * 66 + r] = tf32r(wR[j].z);
            shW[(kq * 4 + 3) * 66 + r] = tf32r(wR[j].w);
        }
        __syncthreads();
        if (c + 1 < NC) loadChunk(c + 1);

#pragma unroll
        for (int kk = 0; kk < 32; kk++) {
            const ulonglong2 a01 = *reinterpret_cast<const ulonglong2*>(&shA[kk * 36 + m0]);
            const ulonglong2 a23 = *reinterpret_cast<const ulonglong2*>(&shA[kk * 36 + m0 + 4]);
            const float2 wv = *reinterpret_cast<const float2*>(&shW[kk * 66 + 2 * ng]);
            const unsigned long long w0 = bcast2_(wv.x);
            const unsigned long long w1 = bcast2_(wv.y);
            acc0[0] = ffma2_(a01.x, w0, acc0[0]);
            acc0[1] = ffma2_(a01.y, w0, acc0[1]);
            acc0[2] = ffma2_(a23.x, w0, acc0[2]);
            acc0[3] = ffma2_(a23.y, w0, acc0[3]);
            acc1[0] = ffma2_(a01.x, w1, acc1[0]);
            acc1[1] = ffma2_(a01.y, w1, acc1[1]);
            acc1[2] = ffma2_(a23.x, w1, acc1[2]);
            acc1[3] = ffma2_(a23.y, w1, acc1[3]);
        }
    }

    const int n0 = nbase + 2 * ng;
#pragma unroll
    for (int r = 0; r < 4; r++) {
        float lo, hi;
        const int m = m0 + 2 * r;
        unpack2_(acc0[r], lo, hi);
        dst[(size_t)m * Nout + n0]           = lo;
        dst[(size_t)(m + 1) * Nout + n0]     = hi;
        unpack2_(acc1[r], lo, hi);
        dst[(size_t)m * Nout + n0 + 1]       = lo;
        dst[(size_t)(m + 1) * Nout + n0 + 1] = hi;
    }
}

// ---------------- LSTM pointwise: 16 gates partial slices -----------------
__device__ __forceinline__ void lstm_update_chunk(int l, int b, int j0)
{
    const int j = j0 + threadIdx.x;
    float gi = g_bsum[l * 4 * H_ + j];
    float gf = g_bsum[l * 4 * H_ + H_ + j];
    float gg = g_bsum[l * 4 * H_ + 2 * H_ + j];
    float go = g_bsum[l * 4 * H_ + 3 * H_ + j];
#pragma unroll
    for (int ks = 0; ks < 16; ks++) {
        const float* p = g_part + (size_t)(ks * 32 + b) * 4 * H_;
        gi += p[j]; gf += p[H_ + j]; gg += p[2 * H_ + j]; go += p[3 * H_ + j];
    }
    float* cp = g_c + (size_t)(l * B_ + b) * H_ + j;
    float* hp = g_h + (size_t)(l * B_ + b) * H_ + j;
    const float si = 1.f / (1.f + expf(-gi));
    const float sf = 1.f / (1.f + expf(-gf));
    const float so = 1.f / (1.f + expf(-go));
    const float cn = sf * (*cp) + si * tanhf(gg);
    *cp = cn;
    *hp = so * tanhf(cn);
}

// ---------------- logits from 4 fc partial slices + log_softmax -----------
__device__ __forceinline__ void ls_row128(float* __restrict__ rowBase,
                                          const float* __restrict__ fcb,
                                          int b, int set, float* red)
{
    float* row = rowBase + (size_t)b * ((long long)T_ * V_);
    const int tid = threadIdx.x;
    const int NV4 = V_ / 4;
    const float* fb = g_fcpart + (size_t)set * 4 * B_ * V_;
    const float4* bb = (const float4*)fcb;
    const float4* p0 = (const float4*)(fb + (size_t)b * V_);
    const float4* p1 = (const float4*)(fb + (size_t)(B_ + b) * V_);
    const float4* p2 = (const float4*)(fb + (size_t)(2 * B_ + b) * V_);
    const float4* p3 = (const float4*)(fb + (size_t)(3 * B_ + b) * V_);
    float4* r4 = (float4*)row;

    float m = -1e30f;
    for (int v = tid; v < NV4; v += 128) {
        const float4 a = bb[v], q0 = p0[v], q1 = p1[v], q2 = p2[v], q3 = p3[v];
        float4 r;
        r.x = a.x + q0.x + q1.x + q2.x + q3.x;
        r.y = a.y + q0.y + q1.y + q2.y + q3.y;
        r.z = a.z + q0.z + q1.z + q2.z + q3.z;
        r.w = a.w + q0.w + q1.w + q2.w + q3.w;
        r4[v] = r;
        m = fmaxf(m, fmaxf(fmaxf(r.x, r.y), fmaxf(r.z, r.w)));
    }
    red[tid] = m; __syncthreads();
    for (int st = 64; st > 0; st >>= 1) {
        if (tid < st) red[tid] = fmaxf(red[tid], red[tid + st]);
        __syncthreads();
    }
    m = red[0];
    __syncthreads();

    float s = 0.f;
    for (int v = tid; v < NV4; v += 128) {
        const float4 r = r4[v];
        s += expf(r.x - m) + expf(r.y - m) + expf(r.z - m) + expf(r.w - m);
    }
    red[tid] = s; __syncthreads();
    for (int st = 64; st > 0; st >>= 1) {
        if (tid < st) red[tid] += red[tid + st];
        __syncthreads();
    }
    const float lse = logf(red[0]);
    __syncthreads();

    for (int v = tid; v < NV4; v += 128) {
        float4 r = r4[v];
        r.x = (r.x - m) - lse;
        r.y = (r.y - m) - lse;
        r.z = (r.z - m) - lse;
        r.w = (r.w - m) - lse;
        r4[v] = r;
    }
}

// ---------------- P0: hW + fc(t-1) + ls(t-2) (no spinners) ---------------
__global__ void __launch_bounds__(128) p0k(
    const float* __restrict__ W1, const float* __restrict__ fcW,
    const float* __restrict__ fcb, float* lsOut,
    int nFc, int fcSet, int lsSet)
{
    __shared__ __align__(16) float shA[32 * 36];
    __shared__ __align__(16) float shW[32 * 66];
    __shared__ float red[128];
    const int bx = blockIdx.x;
    const float* h2 = g_h + 2 * B_ * H_;

    pdl_wait();

    if (bx < 256) {                      // hW partials: 16 slices x 16 tiles
        const int slice = bx & 15, tile = bx >> 4;
        gemm_core32(h2, H_, W1 + E_, E_ + H_, slice * 64, 2, tile * 64,
                    g_partHW + (size_t)slice * B_ * H_, H_, shA, shW);
    } else if (bx < 256 + nFc) {         // fc(t-1): 4 slices x 500 tiles
        const int k = bx - 256;
        const int slice = k / 500, tile = k - slice * 500;
        gemm_core32(h2, H_, fcW, H_, slice * 256, 8, tile * 64,
                    g_fcpart + (size_t)fcSet * 4 * B_ * V_
                             + (size_t)slice * B_ * V_,
                    V_, shA, shW);
    } else {                             // ls(t-2): 32 rows
        ls_row128(lsOut, fcb, bx - 256 - nFc, lsSet, red);
    }
    pdl_trigger();
}

// ---------------- fused attention: 32 blocks x 1024 -----------------------
__global__ void __launch_bounds__(1024) attn_all(
    const float* __restrict__ x, const int* __restrict__ tseq,
    const float* __restrict__ emb, const float* __restrict__ w2,
    const float* __restrict__ b2p, const float* __restrict__ b1, int t)
{
    const int b = blockIdx.x, tid = threadIdx.x;
    __shared__ float hw[H_];
    __shared__ float w2s[H_];
    __shared__ float sc[S1_];
    __shared__ float red4[4];

    pdl_wait();

    {   // hW = b1 + sum of 16 partials
        float v = b1[tid];
#pragma unroll
        for (int ks = 0; ks < 16; ks++)
            v += g_partHW[(size_t)(ks * 32 + b) * H_ + tid];
        hw[tid]  = v;
        w2s[tid] = w2[tid];
    }
    __syncthreads();

    const int lane = tid & 31, w = tid >> 5;
#pragma unroll
    for (int r = 0; r < 4; r++) {
        const int s = r * 32 + w;
        const float* xw = g_xW + ((size_t)b * S1_ + s) * H_;
        float p = 0.f;
#pragma unroll 8
        for (int i = 0; i < 32; i++) {
            const int hh = i * 32 + lane;
            float v = xw[hh] + hw[hh];
            v = fmaxf(v, 0.f);
            p += v * w2s[hh];
        }
#pragma unroll
        for (int o = 16; o > 0; o >>= 1) p += __shfl_xor_sync(0xffffffffu, p, o);
        if (lane == 0) sc[s] = p + b2p[0];
    }
    __syncthreads();

    if (tid < 128) {
        float v = sc[tid];
#pragma unroll
        for (int o = 16; o > 0; o >>= 1) v = fmaxf(v, __shfl_xor_sync(0xffffffffu, v, o));
        if (lane == 0) red4[w] = v;
    }
    __syncthreads();
    const float mx = fmaxf(fmaxf(red4[0], red4[1]), fmaxf(red4[2], red4[3]));
    __syncthreads();
    if (tid < 128) {
        const float sh = sc[tid] - mx;
        sc[tid] = sh;
        float e = expf(sh);
#pragma unroll
        for (int o = 16; o > 0; o >>= 1) e += __shfl_xor_sync(0xffffffffu, e, o);
        if (lane == 0) red4[w] = e;
    }
    __syncthreads();
    const float lse = logf(red4[0] + red4[1] + red4[2] + red4[3]);
    __syncthreads();
    if (tid < 128) sc[tid] -= lse;       // logw
    __syncthreads();

    if (tid < E_) {
        const float* xb = x + (size_t)b * S1_ * E_ + tid;
        float ctx = 0.f;
#pragma unroll 8
        for (int s = 0; s < S1_; s++) ctx += sc[s] * xb[(size_t)s * E_];
        g_inp0[b * 2 * E_ + E_ + tid] = ctx;
        const int tgt = tseq[b * T_ + t];
        g_inp0[b * 2 * E_ + tid] = emb[(size_t)tgt * E_ + tid];
    }
    pdl_trigger();
}

// ---------------- gwk: SHALLOW gates (16 slices x 64 tiles) + fused lp ----
// 1D grid 1280: mains [0,1024) (NC=4..6), spinners [1024,1280) at highest
// bids -> issued after all producers (bid order), so no livelock even though
// grid > resident capacity.
__global__ void __launch_bounds__(128) gwk(
    const float* __restrict__ A1, int ld1, const float* __restrict__ Wi,
    const float* __restrict__ A2, const float* __restrict__ Wh,
    int l, int* cnt)
{
    __shared__ __align__(16) float shA[32 * 36];
    __shared__ __align__(16) float shW[32 * 66];
    const int bx = blockIdx.x;

    pdl_wait();

    if (bx < 1024) {
        const int slice = bx & 15, tile = bx >> 4;
        if (slice < 8) {                 // segA: inp @ Wih, 8 slices of ld1/8
            const int KA = ld1 >> 3;     // 192 (layer 0) or 128
            gemm_core32(A1, ld1, Wi, ld1, slice * KA, KA >> 5, tile * 64,
                        g_part + (size_t)slice * B_ * 4 * H_, 4 * H_, shA, shW);
        } else {                         // segB: h @ Whh, 8 slices of 128
            gemm_core32(A2, H_, Wh, H_, (slice - 8) * 128, 4, tile * 64,
                        g_part + (size_t)slice * B_ * 4 * H_, 4 * H_, shA, shW);
        }
        __threadfence();
        __syncthreads();
        if (threadIdx.x == 0) atomicAdd(cnt, 1);
    } else {
        const int local = bx - 1024;     // 256 spinners
        if (threadIdx.x == 0) {
            while (atomicAdd(cnt, 0) < 1024) __nanosleep(128);
        }
        __syncthreads();
        __threadfence();                 // acquire partials
        lstm_update_chunk(l, local >> 3, (local & 7) * 128);
    }
    pdl_trigger();
}

// ---------------- xW precompute ----------------
__global__ void __launch_bounds__(128) gemm_xw(const float* __restrict__ x,
                                               const float* __restrict__ W1)
{
    __shared__ __align__(16) float shA[32 * 36];
    __shared__ __align__(16) float shW[32 * 66];
    const int z = blockIdx.x >> 4, nx = blockIdx.x & 15;
    gemm_core32(x + (size_t)z * 32 * E_, E_, W1, E_ + H_, 0, E_ / 32, nx * 64,
                g_xW + (size_t)z * 32 * H_, H_, shA, shW);
}

// ---------------- tail: fc(T-1) + ls(T-2), then ls(T-1) -------------------
__global__ void __launch_bounds__(128) fc_tail(
    const float* __restrict__ fcW, const float* __restrict__ fcb,
    float* lsOut, int fcSet, int lsSet)
{
    __shared__ __align__(16) float shA[32 * 36];
    __shared__ __align__(16) float shW[32 * 66];
    __shared__ float red[128];
    pdl_wait();
    const float* h2 = g_h + 2 * B_ * H_;
    if (blockIdx.x < 2000) {
        const int slice = blockIdx.x / 500, tile = blockIdx.x - slice * 500;
        gemm_core32(h2, H_, fcW, H_, slice * 256, 8, tile * 64,
                    g_fcpart + (size_t)fcSet * 4 * B_ * V_ + (size_t)slice * B_ * V_,
                    V_, shA, shW);
    } else {
        ls_row128(lsOut, fcb, blockIdx.x - 2000, lsSet, red);
    }
    pdl_trigger();
}
__global__ void __launch_bounds__(128) ls_tail(float* outBase,
                                               const float* __restrict__ fcb,
                                               int set)
{
    __shared__ float red[128];
    pdl_wait();
    ls_row128(outBase, fcb, blockIdx.x, set, red);
}

// ---------------- init ----------------
__global__ void zero_state()
{
    const int idx = blockIdx.x * 1024 + threadIdx.x;
    if (idx < 3 * B_ * H_) { g_h[idx] = 0.f; g_c[idx] = 0.f; }
    if (idx < 3 * T_) g_cnt[idx] = 0;
}
__global__ void bias_sum(const float* bi0, const float* bh0,
                         const float* bi1, const float* bh1,
                         const float* bi2, const float* bh2)
{
    const int i = blockIdx.x * 1024 + threadIdx.x;
    if (i < 4 * H_) {
        g_bsum[i]          = bi0[i] + bh0[i];
        g_bsum[4 * H_ + i] = bi1[i] + bh1[i];
        g_bsum[8 * H_ + i] = bi2[i] + bh2[i];
    }
}

// ---------------- launch ----------------
extern "C" void kernel_launch(void* const* d_in, const int* in_sizes, int n_in,
                              void* d_out, int out_size)
{
    const float* x    = (const float*)d_in[0];
    const int*   tseq = (const int*)  d_in[1];
    const float* emb  = (const float*)d_in[2];
    const float* W1   = (const float*)d_in[3];   // (H, E+H)
    const float* b1   = (const float*)d_in[4];
    const float* W2   = (const float*)d_in[5];   // (1, H)
    const float* b2   = (const float*)d_in[6];

    const float *fcW, *fcb;
    const float *Wih[3], *Whh[3], *bih[3], *bhh[3];
    int base;
    if (in_sizes[7] == V_ * H_) {          // dict order (expected)
        fcW = (const float*)d_in[7];
        fcb = (const float*)d_in[8];
        base = 9;
    } else {                                // signature order (fallback)
        fcW = (const float*)d_in[19];
        fcb = (const float*)d_in[20];
        base = 7;
    }
    for (int l = 0; l < 3; l++) {
        Wih[l] = (const float*)d_in[base + 4 * l + 0];
        Whh[l] = (const float*)d_in[base + 4 * l + 1];
        bih[l] = (const float*)d_in[base + 4 * l + 2];
        bhh[l] = (const float*)d_in[base + 4 * l + 3];
    }
    float* out = (float*)d_out;

    float *inp0, *h;
    int* cntBase;
    cudaGetSymbolAddress((void**)&inp0,    g_inp0);
    cudaGetSymbolAddress((void**)&h,       g_h);
    cudaGetSymbolAddress((void**)&cntBase, g_cnt);
    float* h0 = h;
    float* h1 = h + B_ * H_;

    zero_state<<<96, 1024>>>();
    bias_sum<<<4, 1024>>>(bih[0], bhh[0], bih[1], bhh[1], bih[2], bhh[2]);
    gemm_xw<<<2048, 128>>>(x, W1);

    // PDL launch config (Programmatic Stream Serialization)
    cudaLaunchAttribute pdlAttr[1];
    pdlAttr[0].id = cudaLaunchAttributeProgrammaticStreamSerialization;
    pdlAttr[0].val.programmaticStreamSerializationAllowed = 1;

    auto mkCfg = [&](unsigned grid, unsigned block) {
        cudaLaunchConfig_t cfg = {};
        cfg.gridDim  = dim3(grid, 1, 1);
        cfg.blockDim = dim3(block, 1, 1);
        cfg.dynamicSmemBytes = 0;
        cfg.stream = 0;
        cfg.attrs = pdlAttr;
        cfg.numAttrs = 1;
        return cfg;
    };

    for (int t = 0; t < T_; t++) {
        const int nFc   = (t > 0)  ? 2000 : 0;
        const int nLs   = (t >= 2) ? 32   : 0;
        const int fcSet = (t - 1) & 1;
        const int lsSet = (t - 2) & 1;
        float* lsOut = (t >= 2) ? (out + (size_t)(t - 2) * V_) : out;

        {   // P0: hW + fc(t-1) + ls(t-2)
            cudaLaunchConfig_t cfg = mkCfg(256 + nFc + nLs, 128);
            cudaLaunchKernelEx(&cfg, p0k, W1, fcW, fcb, lsOut, nFc, fcSet, lsSet);
        }
        {   // attention
            cudaLaunchConfig_t cfg = mkCfg(B_, 1024);
            cudaLaunchKernelEx(&cfg, attn_all, x, tseq, emb, W2, b2, b1, t);
        }
        {   // layer 0: inp0@Wih0 + h0@Whh0 (16 shallow slices) + lp0 spinners
            cudaLaunchConfig_t cfg = mkCfg(1280, 128);
            cudaLaunchKernelEx(&cfg, gwk, (const float*)inp0, 2 * E_, Wih[0],
                               (const float*)h0, Whh[0], 0, cntBase + t * 3 + 0);
        }
        {   // layer 1
            cudaLaunchConfig_t cfg = mkCfg(1280, 128);
            cudaLaunchKernelEx(&cfg, gwk, (const float*)h0, H_, Wih[1],
                               (const float*)h1, Whh[1], 1, cntBase + t * 3 + 1);
        }
        {   // layer 2
            cudaLaunchConfig_t cfg = mkCfg(1280, 128);
            cudaLaunchKernelEx(&cfg, gwk, (const float*)h1, H_, Wih[2],
                               (const float*)(h + 2 * B_ * H_), Whh[2], 2,
                               cntBase + t * 3 + 2);
        }
    }

    // tail: fc(T-1) + ls(T-2), then ls(T-1)
    {
        cudaLaunchConfig_t cfg = mkCfg(2032, 128);
        cudaLaunchKernelEx(&cfg, fc_tail, fcW, fcb,
                           out + (size_t)(T_ - 2) * V_,
                           (T_ - 1) & 1, (T_ - 2) & 1);
    }
    {
        cudaLaunchConfig_t cfg = mkCfg(B_, 128);
        cudaLaunchKernelEx(&cfg, ls_tail, out + (size_t)(T_ - 1) * V_, fcb,
                           (T_ - 1) & 1);
    }
}